// round 16
// baseline (speedup 1.0000x reference)
#include <cuda_runtime.h>
#include <cstdint>

// Problem constants (fixed by setup_inputs): B=8, H=W=512, D=32, K=64
#define BATCH   8
#define NPIX    (512 * 512)
#define DIM     32
#define KINST   64
#define MARGIN  0.25f

#define NSM     148
#define MAXBPB  296
#define THREADS 128
#define WARPS   4

// bulk-copy staging
#define NSTG      5
#define SPIX      64                     // pixels per stage
#define STG_BYTES (SPIX * DIM * 4)       // 8192
#define LAB_BYTES (SPIX * 4)             // 256

// dynamic smem layout (16B-aligned sections)
#define OFF_STAGE 0
#define OFF_BINS  (NSTG * STG_BYTES)                      // 40960
#define OFF_SLAB  (OFF_BINS + WARPS * KINST * DIM * 4)    // 73728
#define OFF_MBAR  (OFF_SLAB + NSTG * LAB_BYTES)           // 75008
#define OFF_HCNT  (OFF_MBAR + 2 * NSTG * 8)               // 75088
#define DSMEM     (OFF_HCNT + KINST * 4)                  // 75344

#define RBLOCKS 64                 // reduce/finalize blocks (8 slices x 8 batches)

// Scratch (__device__ globals: allocs are banned)
__device__ float g_part_sums[MAXBPB * BATCH * KINST * DIM];
__device__ float g_part_cnts[MAXBPB * BATCH * KINST];
__device__ float g_sums[BATCH * KINST * DIM];
__device__ int   g_done  = 0;
__device__ int   g_done2 = 0;

// ---------------------------------------------------------------------------
__global__ void nop_kernel() {}

// ---------------------------------------------------------------------------
// mbarrier / bulk-copy primitives
// ---------------------------------------------------------------------------
__device__ __forceinline__ uint32_t smem_u32(const void* p) {
    uint32_t a;
    asm("{ .reg .u64 t; cvta.to.shared.u64 t, %1; cvt.u32.u64 %0, t; }"
        : "=r"(a) : "l"(p));
    return a;
}
__device__ __forceinline__ void mbar_init(uint32_t a, uint32_t cnt) {
    asm volatile("mbarrier.init.shared.b64 [%0], %1;" :: "r"(a), "r"(cnt) : "memory");
}
__device__ __forceinline__ void mbar_expect_tx(uint32_t a, uint32_t bytes) {
    asm volatile("mbarrier.arrive.expect_tx.shared.b64 _, [%0], %1;"
                 :: "r"(a), "r"(bytes) : "memory");
}
__device__ __forceinline__ void mbar_arrive(uint32_t a) {
    asm volatile("mbarrier.arrive.shared.b64 _, [%0];" :: "r"(a) : "memory");
}
__device__ __forceinline__ void mbar_wait(uint32_t a, uint32_t ph) {
    asm volatile(
        "{\n\t.reg .pred P;\n"
        "WL%=:\n\t"
        "mbarrier.try_wait.parity.shared.b64 P, [%0], %1;\n\t"
        "@P bra WD%=;\n\t"
        "bra WL%=;\n"
        "WD%=:\n\t}"
        :: "r"(a), "r"(ph) : "memory");
}
__device__ __forceinline__ void bulk_g2s(uint32_t dst, const void* src,
                                         uint32_t bytes, uint32_t mbar) {
    asm volatile(
        "cp.async.bulk.shared::cluster.global.mbarrier::complete_tx::bytes "
        "[%0], [%1], %2, [%3];"
        :: "r"(dst), "l"(src), "r"(bytes), "r"(mbar) : "memory");
}

// ---------------------------------------------------------------------------
// accum: bulk-copy pipeline (5 x 8KB stages) -> smem -> warp-private rotated
// bins + per-thread label dedup/batched RMW. NEW: in-flight label histogram
// (sub==0 lanes atomicAdd the 4 group labels into a block-shared 64-counter
// hist) -> per-block count partials; deletes the separate hist pass.
// ---------------------------------------------------------------------------
__global__ __launch_bounds__(THREADS)
void accum_kernel(const float* __restrict__ emb, const int* __restrict__ lab,
                  int chunk) {
    extern __shared__ __align__(16) char dsm[];
    float4* stage = (float4*)(dsm + OFF_STAGE);
    float*  bins  = (float*)(dsm + OFF_BINS);
    int*    slab  = (int*)(dsm + OFF_SLAB);
    int*    hcnt  = (int*)(dsm + OFF_HCNT);

    const int tid  = threadIdx.x;
    const int w    = tid >> 5;
    const int lane = tid & 31;
    const int sub  = lane & 7;
    const int pix  = lane >> 3;
    const int b    = blockIdx.y;

    for (int i = tid; i < WARPS * KINST * DIM; i += THREADS)
        bins[i] = 0.0f;
    for (int i = tid; i < KINST; i += THREADS)
        hcnt[i] = 0;

    const uint32_t mb0 = smem_u32(dsm + OFF_MBAR);
    if (tid == 0) {
#pragma unroll
        for (int s = 0; s < NSTG; s++) {
            mbar_init(mb0 + 8 * s, 1);
            mbar_init(mb0 + 8 * (NSTG + s), WARPS);
        }
        asm volatile("fence.proxy.async.shared::cta;" ::: "memory");
    }
    __syncthreads();

    const int p0 = blockIdx.x * chunk;
    int p1 = p0 + chunk; if (p1 > NPIX) p1 = NPIX;
    if (p1 <= p0) return;
    const int nst = (p1 - p0) / SPIX;

    const float* gsrc = emb + ((size_t)b * NPIX + p0) * DIM;
    const int*   lsrc = lab + (size_t)b * NPIX + p0;

    const uint32_t stage0 = smem_u32(stage);
    const uint32_t slab0  = smem_u32(slab);

    if (tid == 0) {
        for (int s = 0; s < NSTG && s < nst; s++) {
            mbar_expect_tx(mb0 + 8 * s, STG_BYTES + LAB_BYTES);
            bulk_g2s(stage0 + s * STG_BYTES, gsrc + (size_t)s * SPIX * DIM,
                     STG_BYTES, mb0 + 8 * s);
            bulk_g2s(slab0 + s * LAB_BYTES, lsrc + s * SPIX,
                     LAB_BYTES, mb0 + 8 * s);
        }
    }

    float* mybin = bins + w * (KINST * DIM);
    uint32_t fph = 0, eph = 0;
    int s = 0;

    for (int i = 0; i < nst; i++) {
        mbar_wait(mb0 + 8 * s, (fph >> s) & 1u);
        fph ^= (1u << s);

        const float4* st = &stage[(size_t)s * SPIX * 8];
        const int*    sl = &slab[s * SPIX];

        // load 4 group values + labels
        const int base = w * 16 + pix;
        int    k0 = sl[base +  0], k1 = sl[base +  4];
        int    k2 = sl[base +  8], k3 = sl[base + 12];
        float4 v0 = st[(base +  0) * 8 + sub];
        float4 v1 = st[(base +  4) * 8 + sub];
        float4 v2 = st[(base +  8) * 8 + sub];
        float4 v3 = st[(base + 12) * 8 + sub];

        // in-flight histogram: one lane per pixel (sub==0 covers pix 0..3)
        if (sub == 0) {
            atomicAdd(&hcnt[k0], 1);
            atomicAdd(&hcnt[k1], 1);
            atomicAdd(&hcnt[k2], 1);
            atomicAdd(&hcnt[k3], 1);
        }

        // dedup: merge later groups with equal label into the earliest one
        bool a1 = true, a2 = true, a3 = true;
        if (k1 == k0) { v0.x += v1.x; v0.y += v1.y; v0.z += v1.z; v0.w += v1.w; a1 = false; }
        if (k2 == k0) { v0.x += v2.x; v0.y += v2.y; v0.z += v2.z; v0.w += v2.w; a2 = false; }
        else if (k2 == k1) { v1.x += v2.x; v1.y += v2.y; v1.z += v2.z; v1.w += v2.w; a2 = false; }
        if (k3 == k0) { v0.x += v3.x; v0.y += v3.y; v0.z += v3.z; v0.w += v3.w; a3 = false; }
        else if (k3 == k1) { v1.x += v3.x; v1.y += v3.y; v1.z += v3.z; v1.w += v3.w; a3 = false; }
        else if (k3 == k2) { v2.x += v3.x; v2.y += v3.y; v2.z += v3.z; v2.w += v3.w; a3 = false; }

        // active groups have distinct k per thread -> batched RMW
        const int sb = sub << 2;
        float4* bp0 = (float4*)&mybin[(k0 << 5) + ((sb + ((k0 & 3) << 3)) & 31)];
        float4* bp1 = (float4*)&mybin[(k1 << 5) + ((sb + ((k1 & 3) << 3)) & 31)];
        float4* bp2 = (float4*)&mybin[(k2 << 5) + ((sb + ((k2 & 3) << 3)) & 31)];
        float4* bp3 = (float4*)&mybin[(k3 << 5) + ((sb + ((k3 & 3) << 3)) & 31)];
        float4 c0 = *bp0;
        float4 c1, c2, c3;
        if (a1) c1 = *bp1;
        if (a2) c2 = *bp2;
        if (a3) c3 = *bp3;
        c0.x += v0.x; c0.y += v0.y; c0.z += v0.z; c0.w += v0.w;
        if (a1) { c1.x += v1.x; c1.y += v1.y; c1.z += v1.z; c1.w += v1.w; }
        if (a2) { c2.x += v2.x; c2.y += v2.y; c2.z += v2.z; c2.w += v2.w; }
        if (a3) { c3.x += v3.x; c3.y += v3.y; c3.z += v3.z; c3.w += v3.w; }
        *bp0 = c0;
        if (a1) *bp1 = c1;
        if (a2) *bp2 = c2;
        if (a3) *bp3 = c3;

        __syncwarp();
        if (lane == 0) mbar_arrive(mb0 + 8 * (NSTG + s));

        if (tid == 0 && i + NSTG < nst) {
            mbar_wait(mb0 + 8 * (NSTG + s), (eph >> s) & 1u);
            eph ^= (1u << s);
            mbar_expect_tx(mb0 + 8 * s, STG_BYTES + LAB_BYTES);
            bulk_g2s(stage0 + s * STG_BYTES,
                     gsrc + (size_t)(i + NSTG) * SPIX * DIM,
                     STG_BYTES, mb0 + 8 * s);
            bulk_g2s(slab0 + s * LAB_BYTES, lsrc + (i + NSTG) * SPIX,
                     LAB_BYTES, mb0 + 8 * s);
        }
        if (++s == NSTG) s = 0;
    }
    __syncthreads();

    float* dst = &g_part_sums[((size_t)blockIdx.x * BATCH + b) * KINST * DIM];
    for (int i = tid; i < KINST * DIM; i += THREADS) {
        const int k = i >> 5, d = i & 31;
        const int phys = (k << 5) + ((d + ((k & 3) << 3)) & 31);
        dst[i] = bins[0 * KINST * DIM + phys] + bins[1 * KINST * DIM + phys]
               + bins[2 * KINST * DIM + phys] + bins[3 * KINST * DIM + phys];
    }
    float* dct = &g_part_cnts[((size_t)blockIdx.x * BATCH + b) * KINST];
    for (int i = tid; i < KINST; i += THREADS)
        dct[i] = (float)hcnt[i];
}

// ---------------------------------------------------------------------------
// reduce + finalize: 64 blocks (block r -> batch r>>3, slice r&7).
// Pre-gate: fold this block's share of partial sums into g_sums, AND fold
// counts for its own batch (local, no gate needed). Post-gate: finalize the
// (slice, batch) pair-cells. Cleanup resets flags each graph replay.
// ---------------------------------------------------------------------------
#define CSTRIDE 33

__global__ __launch_bounds__(256)
void reduce_finalize_kernel(int nparts, float* __restrict__ out) {
    const int tid = threadIdx.x;
    const int i = blockIdx.x * 256 + tid;
    const int b     = blockIdx.x >> 3;
    const int slice = blockIdx.x & 7;

    __shared__ float cnt[KINST];

    if (blockIdx.x == 0 && tid == 0) out[0] = 0.0f;

    // ---- pre-gate 1: fold partial sums (thread i owns one (b,k,d) slot) ----
    float s = 0.0f;
#pragma unroll 8
    for (int j = 0; j < nparts; j++)
        s += g_part_sums[(size_t)j * (BATCH * KINST * DIM) + i];
    g_sums[i] = s;

    // ---- pre-gate 2: fold counts for this block's batch (no gate needed) ----
    for (int q = tid; q < KINST; q += 256) {
        float c = 0.0f;
#pragma unroll 4
        for (int j = 0; j < nparts; j++)
            c += g_part_cnts[(j * BATCH + b) * KINST + q];
        cnt[q] = c;
    }

    // ---- gate: wait until ALL blocks finished folding sums ----
    __threadfence();
    __syncthreads();
    if (tid == 0) {
        atomicAdd(&g_done, 1);
        while (*(volatile int*)&g_done < RBLOCKS) __nanosleep(64);
    }
    __syncthreads();
    __threadfence();

    // ---- post-gate: finalize slice of batch b ----
    __shared__ float cc[KINST * CSTRIDE];
    __shared__ float wsum[8];

    for (int q = tid; q < KINST * DIM; q += 256) {
        const int k = q >> 5, d = q & 31;
        cc[k * CSTRIDE + d] =
            g_sums[b * KINST * DIM + q] / fmaxf(cnt[k], 1.0f);
    }
    __syncthreads();

    const int t0 = slice * (KINST * KINST / 8);   // 512 cells per slice
    float acc = 0.0f;
    for (int t = t0 + tid; t < t0 + KINST * KINST / 8; t += 256) {
        const int ii = t >> 6, jj = t & 63;
        if (jj > ii && cnt[ii] > 0.5f && cnt[jj] > 0.5f) {
            float dsum = 0.0f;
#pragma unroll
            for (int d = 0; d < DIM; d++)
                dsum += fabsf(cc[ii * CSTRIDE + d] - cc[jj * CSTRIDE + d]);
            const float h = fmaxf(0.0f, MARGIN - dsum);
            acc += h * h;
        }
    }
#pragma unroll
    for (int off = 16; off > 0; off >>= 1)
        acc += __shfl_xor_sync(0xFFFFFFFFu, acc, off);
    if ((tid & 31) == 0) wsum[tid >> 5] = acc;
    __syncthreads();

    if (tid == 0) {
        float n = 0.0f;
#pragma unroll
        for (int k = 0; k < KINST; k++) n += (cnt[k] > 0.5f) ? 1.0f : 0.0f;
        const float ncomp = n * (n - 1.0f) * 0.5f;
        float part = 0.0f;
#pragma unroll
        for (int ww = 0; ww < 8; ww++) part += wsum[ww];
        atomicAdd(out, part / (ncomp * (float)BATCH));

        // cleanup: last block resets flags for next graph replay
        __threadfence();
        if (atomicAdd(&g_done2, 1) == RBLOCKS - 1) {
            g_done  = 0;
            g_done2 = 0;
        }
    }
}

// ---------------------------------------------------------------------------
extern "C" void kernel_launch(void* const* d_in, const int* in_sizes, int n_in,
                              void* d_out, int out_size) {
    const float* emb = (const float*)d_in[0];
    const int*   lab = (const int*)d_in[1];
    float*       out = (float*)d_out;
    (void)in_sizes; (void)n_in; (void)out_size;

    cudaFuncSetAttribute(accum_kernel,
                         cudaFuncAttributeMaxDynamicSharedMemorySize, DSMEM);
    int occ = 0;
    cudaOccupancyMaxActiveBlocksPerMultiprocessor(&occ, accum_kernel, THREADS, DSMEM);
    if (occ < 1) occ = 1;
    int bpb = (NSM * occ) / BATCH;
    if (bpb < 1)      bpb = 1;
    if (bpb > MAXBPB) bpb = MAXBPB;
    int chunk = (NPIX + bpb - 1) / bpb;
    chunk = (chunk + SPIX - 1) & ~(SPIX - 1);   // full stages only

    // 4-kernel graph: profiled launch index (L=15/27, %4 == 3) lands on
    // reduce_finalize — this round diagnoses the ~18us non-accum residual.
    accum_kernel<<<dim3(bpb, BATCH), THREADS, DSMEM>>>(emb, lab, chunk); // idx 0
    nop_kernel<<<1, 32>>>();                                             // idx 1
    nop_kernel<<<1, 32>>>();                                             // idx 2
    reduce_finalize_kernel<<<RBLOCKS, 256>>>(bpb, out);                  // idx 3 <- profiled
}

// round 17
// speedup vs baseline: 1.1061x; 1.1061x over previous
#include <cuda_runtime.h>
#include <cstdint>

// Problem constants (fixed by setup_inputs): B=8, H=W=512, D=32, K=64
#define BATCH   8
#define NPIX    (512 * 512)
#define DIM     32
#define KINST   64
#define MARGIN  0.25f

#define NSM     148
#define MAXBPB  296
#define THREADS 128
#define WARPS   4

// bulk-copy staging (proven config)
#define NSTG      5
#define SPIX      64                     // pixels per stage
#define STG_BYTES (SPIX * DIM * 4)       // 8192
#define LAB_BYTES (SPIX * 4)             // 256

// dynamic smem layout (16B-aligned sections)
#define OFF_STAGE 0
#define OFF_BINS  (NSTG * STG_BYTES)                      // 40960
#define OFF_SLAB  (OFF_BINS + WARPS * KINST * DIM * 4)    // 73728
#define OFF_MBAR  (OFF_SLAB + NSTG * LAB_BYTES)           // 75008
#define OFF_HCNT  (OFF_MBAR + 2 * NSTG * 8)               // 75088
#define DSMEM     (OFF_HCNT + KINST * 4)                  // 75344

#define NSLOT   (BATCH * KINST * DIM)    // 16384
#define NCSLOT  (BATCH * KINST)          // 512
#define JGROUPS 8                        // second-level fan-in

// Scratch (__device__ globals: allocs are banned)
__device__ float g_part_sums[MAXBPB * BATCH * KINST * DIM];
__device__ float g_part_cnts[MAXBPB * BATCH * KINST];
__device__ float g_sums2[JGROUPS * NSLOT];
__device__ float g_cnts2[JGROUPS * NCSLOT];

// ---------------------------------------------------------------------------
__global__ void nop_kernel() {}

// ---------------------------------------------------------------------------
// mbarrier / bulk-copy primitives
// ---------------------------------------------------------------------------
__device__ __forceinline__ uint32_t smem_u32(const void* p) {
    uint32_t a;
    asm("{ .reg .u64 t; cvta.to.shared.u64 t, %1; cvt.u32.u64 %0, t; }"
        : "=r"(a) : "l"(p));
    return a;
}
__device__ __forceinline__ void mbar_init(uint32_t a, uint32_t cnt) {
    asm volatile("mbarrier.init.shared.b64 [%0], %1;" :: "r"(a), "r"(cnt) : "memory");
}
__device__ __forceinline__ void mbar_expect_tx(uint32_t a, uint32_t bytes) {
    asm volatile("mbarrier.arrive.expect_tx.shared.b64 _, [%0], %1;"
                 :: "r"(a), "r"(bytes) : "memory");
}
__device__ __forceinline__ void mbar_arrive(uint32_t a) {
    asm volatile("mbarrier.arrive.shared.b64 _, [%0];" :: "r"(a) : "memory");
}
__device__ __forceinline__ void mbar_wait(uint32_t a, uint32_t ph) {
    asm volatile(
        "{\n\t.reg .pred P;\n"
        "WL%=:\n\t"
        "mbarrier.try_wait.parity.shared.b64 P, [%0], %1;\n\t"
        "@P bra WD%=;\n\t"
        "bra WL%=;\n"
        "WD%=:\n\t}"
        :: "r"(a), "r"(ph) : "memory");
}
__device__ __forceinline__ void bulk_g2s(uint32_t dst, const void* src,
                                         uint32_t bytes, uint32_t mbar) {
    asm volatile(
        "cp.async.bulk.shared::cluster.global.mbarrier::complete_tx::bytes "
        "[%0], [%1], %2, [%3];"
        :: "r"(dst), "l"(src), "r"(bytes), "r"(mbar) : "memory");
}

// ---------------------------------------------------------------------------
// accum (UNCHANGED from R15, proven): bulk-copy pipeline -> warp-private
// rotated bins + dedup/batched RMW + in-flight label histogram.
// ---------------------------------------------------------------------------
__global__ __launch_bounds__(THREADS)
void accum_kernel(const float* __restrict__ emb, const int* __restrict__ lab,
                  int chunk) {
    extern __shared__ __align__(16) char dsm[];
    float4* stage = (float4*)(dsm + OFF_STAGE);
    float*  bins  = (float*)(dsm + OFF_BINS);
    int*    slab  = (int*)(dsm + OFF_SLAB);
    int*    hcnt  = (int*)(dsm + OFF_HCNT);

    const int tid  = threadIdx.x;
    const int w    = tid >> 5;
    const int lane = tid & 31;
    const int sub  = lane & 7;
    const int pix  = lane >> 3;
    const int b    = blockIdx.y;

    for (int i = tid; i < WARPS * KINST * DIM; i += THREADS)
        bins[i] = 0.0f;
    for (int i = tid; i < KINST; i += THREADS)
        hcnt[i] = 0;

    const uint32_t mb0 = smem_u32(dsm + OFF_MBAR);
    if (tid == 0) {
#pragma unroll
        for (int s = 0; s < NSTG; s++) {
            mbar_init(mb0 + 8 * s, 1);
            mbar_init(mb0 + 8 * (NSTG + s), WARPS);
        }
        asm volatile("fence.proxy.async.shared::cta;" ::: "memory");
    }
    __syncthreads();

    const int p0 = blockIdx.x * chunk;
    int p1 = p0 + chunk; if (p1 > NPIX) p1 = NPIX;
    if (p1 <= p0) return;
    const int nst = (p1 - p0) / SPIX;

    const float* gsrc = emb + ((size_t)b * NPIX + p0) * DIM;
    const int*   lsrc = lab + (size_t)b * NPIX + p0;

    const uint32_t stage0 = smem_u32(stage);
    const uint32_t slab0  = smem_u32(slab);

    if (tid == 0) {
        for (int s = 0; s < NSTG && s < nst; s++) {
            mbar_expect_tx(mb0 + 8 * s, STG_BYTES + LAB_BYTES);
            bulk_g2s(stage0 + s * STG_BYTES, gsrc + (size_t)s * SPIX * DIM,
                     STG_BYTES, mb0 + 8 * s);
            bulk_g2s(slab0 + s * LAB_BYTES, lsrc + s * SPIX,
                     LAB_BYTES, mb0 + 8 * s);
        }
    }

    float* mybin = bins + w * (KINST * DIM);
    uint32_t fph = 0, eph = 0;
    int s = 0;

    for (int i = 0; i < nst; i++) {
        mbar_wait(mb0 + 8 * s, (fph >> s) & 1u);
        fph ^= (1u << s);

        const float4* st = &stage[(size_t)s * SPIX * 8];
        const int*    sl = &slab[s * SPIX];

        const int base = w * 16 + pix;
        int    k0 = sl[base +  0], k1 = sl[base +  4];
        int    k2 = sl[base +  8], k3 = sl[base + 12];
        float4 v0 = st[(base +  0) * 8 + sub];
        float4 v1 = st[(base +  4) * 8 + sub];
        float4 v2 = st[(base +  8) * 8 + sub];
        float4 v3 = st[(base + 12) * 8 + sub];

        if (sub == 0) {
            atomicAdd(&hcnt[k0], 1);
            atomicAdd(&hcnt[k1], 1);
            atomicAdd(&hcnt[k2], 1);
            atomicAdd(&hcnt[k3], 1);
        }

        bool a1 = true, a2 = true, a3 = true;
        if (k1 == k0) { v0.x += v1.x; v0.y += v1.y; v0.z += v1.z; v0.w += v1.w; a1 = false; }
        if (k2 == k0) { v0.x += v2.x; v0.y += v2.y; v0.z += v2.z; v0.w += v2.w; a2 = false; }
        else if (k2 == k1) { v1.x += v2.x; v1.y += v2.y; v1.z += v2.z; v1.w += v2.w; a2 = false; }
        if (k3 == k0) { v0.x += v3.x; v0.y += v3.y; v0.z += v3.z; v0.w += v3.w; a3 = false; }
        else if (k3 == k1) { v1.x += v3.x; v1.y += v3.y; v1.z += v3.z; v1.w += v3.w; a3 = false; }
        else if (k3 == k2) { v2.x += v3.x; v2.y += v3.y; v2.z += v3.z; v2.w += v3.w; a3 = false; }

        const int sb = sub << 2;
        float4* bp0 = (float4*)&mybin[(k0 << 5) + ((sb + ((k0 & 3) << 3)) & 31)];
        float4* bp1 = (float4*)&mybin[(k1 << 5) + ((sb + ((k1 & 3) << 3)) & 31)];
        float4* bp2 = (float4*)&mybin[(k2 << 5) + ((sb + ((k2 & 3) << 3)) & 31)];
        float4* bp3 = (float4*)&mybin[(k3 << 5) + ((sb + ((k3 & 3) << 3)) & 31)];
        float4 c0 = *bp0;
        float4 c1, c2, c3;
        if (a1) c1 = *bp1;
        if (a2) c2 = *bp2;
        if (a3) c3 = *bp3;
        c0.x += v0.x; c0.y += v0.y; c0.z += v0.z; c0.w += v0.w;
        if (a1) { c1.x += v1.x; c1.y += v1.y; c1.z += v1.z; c1.w += v1.w; }
        if (a2) { c2.x += v2.x; c2.y += v2.y; c2.z += v2.z; c2.w += v2.w; }
        if (a3) { c3.x += v3.x; c3.y += v3.y; c3.z += v3.z; c3.w += v3.w; }
        *bp0 = c0;
        if (a1) *bp1 = c1;
        if (a2) *bp2 = c2;
        if (a3) *bp3 = c3;

        __syncwarp();
        if (lane == 0) mbar_arrive(mb0 + 8 * (NSTG + s));

        if (tid == 0 && i + NSTG < nst) {
            mbar_wait(mb0 + 8 * (NSTG + s), (eph >> s) & 1u);
            eph ^= (1u << s);
            mbar_expect_tx(mb0 + 8 * s, STG_BYTES + LAB_BYTES);
            bulk_g2s(stage0 + s * STG_BYTES,
                     gsrc + (size_t)(i + NSTG) * SPIX * DIM,
                     STG_BYTES, mb0 + 8 * s);
            bulk_g2s(slab0 + s * LAB_BYTES, lsrc + (i + NSTG) * SPIX,
                     LAB_BYTES, mb0 + 8 * s);
        }
        if (++s == NSTG) s = 0;
    }
    __syncthreads();

    float* dst = &g_part_sums[((size_t)blockIdx.x * BATCH + b) * KINST * DIM];
    for (int i = tid; i < KINST * DIM; i += THREADS) {
        const int k = i >> 5, d = i & 31;
        const int phys = (k << 5) + ((d + ((k & 3) << 3)) & 31);
        dst[i] = bins[0 * KINST * DIM + phys] + bins[1 * KINST * DIM + phys]
               + bins[2 * KINST * DIM + phys] + bins[3 * KINST * DIM + phys];
    }
    float* dct = &g_part_cnts[((size_t)blockIdx.x * BATCH + b) * KINST];
    for (int i = tid; i < KINST; i += THREADS)
        dct[i] = (float)hcnt[i];
}

// ---------------------------------------------------------------------------
// reduce_wide: first-level fold, wide and shallow. grid = (64, JGROUPS).
// Block (x, jg) folds j in [jg*jgsz, min(+jgsz, nparts)) for slots
// x*256..x*256+255 -> g_sums2[jg]. Counts likewise. <=7 independent loads
// per thread = one latency wave. Also zeroes out[0].
// ---------------------------------------------------------------------------
__global__ __launch_bounds__(256)
void reduce_wide_kernel(int nparts, int jgsz, float* __restrict__ out) {
    const int tid = threadIdx.x;
    const int i   = blockIdx.x * 256 + tid;     // slot 0..16383
    const int jg  = blockIdx.y;

    if (i == 0 && jg == 0) out[0] = 0.0f;

    const int j0 = jg * jgsz;
    int j1 = j0 + jgsz; if (j1 > nparts) j1 = nparts;

    float s = 0.0f;
    for (int j = j0; j < j1; j++)
        s += g_part_sums[(size_t)j * NSLOT + i];
    g_sums2[jg * NSLOT + i] = s;

    if (i < NCSLOT) {
        float c = 0.0f;
        for (int j = j0; j < j1; j++)
            c += g_part_cnts[j * NCSLOT + i];
        g_cnts2[jg * NCSLOT + i] = c;
    }
}

// ---------------------------------------------------------------------------
// finalize: 64 blocks (block r -> batch r>>3, slice r&7). Folds only the
// JGROUPS=8 second-level partials per slot (8 independent loads), builds
// centroids in smem (stride 33), evaluates its 512 pair-cells, atomicAdds
// into out (zeroed by reduce_wide; ordered by the kernel boundary).
// ---------------------------------------------------------------------------
#define CSTRIDE 33

__global__ __launch_bounds__(256)
void finalize_kernel(float* __restrict__ out) {
    __shared__ float cc[KINST * CSTRIDE];
    __shared__ float cnt[KINST];
    __shared__ float wsum[8];

    const int tid   = threadIdx.x;
    const int b     = blockIdx.x >> 3;
    const int slice = blockIdx.x & 7;

    for (int q = tid; q < KINST; q += 256) {
        float c = 0.0f;
#pragma unroll
        for (int jg = 0; jg < JGROUPS; jg++)
            c += g_cnts2[jg * NCSLOT + b * KINST + q];
        cnt[q] = c;
    }
    __syncthreads();

    for (int q = tid; q < KINST * DIM; q += 256) {
        float s = 0.0f;
#pragma unroll
        for (int jg = 0; jg < JGROUPS; jg++)
            s += g_sums2[jg * NSLOT + b * KINST * DIM + q];
        const int k = q >> 5, d = q & 31;
        cc[k * CSTRIDE + d] = s / fmaxf(cnt[k], 1.0f);
    }
    __syncthreads();

    const int t0 = slice * (KINST * KINST / 8);   // 512 cells per slice
    float acc = 0.0f;
    for (int t = t0 + tid; t < t0 + KINST * KINST / 8; t += 256) {
        const int ii = t >> 6, jj = t & 63;
        if (jj > ii && cnt[ii] > 0.5f && cnt[jj] > 0.5f) {
            float dsum = 0.0f;
#pragma unroll
            for (int d = 0; d < DIM; d++)
                dsum += fabsf(cc[ii * CSTRIDE + d] - cc[jj * CSTRIDE + d]);
            const float h = fmaxf(0.0f, MARGIN - dsum);
            acc += h * h;
        }
    }
#pragma unroll
    for (int off = 16; off > 0; off >>= 1)
        acc += __shfl_xor_sync(0xFFFFFFFFu, acc, off);
    if ((tid & 31) == 0) wsum[tid >> 5] = acc;
    __syncthreads();

    if (tid == 0) {
        float n = 0.0f;
#pragma unroll
        for (int k = 0; k < KINST; k++) n += (cnt[k] > 0.5f) ? 1.0f : 0.0f;
        const float ncomp = n * (n - 1.0f) * 0.5f;
        float part = 0.0f;
#pragma unroll
        for (int ww = 0; ww < 8; ww++) part += wsum[ww];
        atomicAdd(out, part / (ncomp * (float)BATCH));
    }
}

// ---------------------------------------------------------------------------
extern "C" void kernel_launch(void* const* d_in, const int* in_sizes, int n_in,
                              void* d_out, int out_size) {
    const float* emb = (const float*)d_in[0];
    const int*   lab = (const int*)d_in[1];
    float*       out = (float*)d_out;
    (void)in_sizes; (void)n_in; (void)out_size;

    cudaFuncSetAttribute(accum_kernel,
                         cudaFuncAttributeMaxDynamicSharedMemorySize, DSMEM);
    int occ = 0;
    cudaOccupancyMaxActiveBlocksPerMultiprocessor(&occ, accum_kernel, THREADS, DSMEM);
    if (occ < 1) occ = 1;
    int bpb = (NSM * occ) / BATCH;
    if (bpb < 1)      bpb = 1;
    if (bpb > MAXBPB) bpb = MAXBPB;
    int chunk = (NPIX + bpb - 1) / bpb;
    chunk = (chunk + SPIX - 1) & ~(SPIX - 1);   // full stages only

    const int jgsz = (bpb + JGROUPS - 1) / JGROUPS;

    // 4-kernel graph: profiled launch index (%4 == 3) = finalize.
    accum_kernel<<<dim3(bpb, BATCH), THREADS, DSMEM>>>(emb, lab, chunk);   // idx 0
    reduce_wide_kernel<<<dim3(64, JGROUPS), 256>>>(bpb, jgsz, out);        // idx 1
    nop_kernel<<<1, 32>>>();                                               // idx 2
    finalize_kernel<<<64, 256>>>(out);                                     // idx 3 <- profiled
}